// round 5
// baseline (speedup 1.0000x reference)
#include <cuda_runtime.h>
#include <cuda_bf16.h>
#include <cstdint>

#define NN 30000
#define NE 300000
#define NB 64

// ---------------- scratch (__device__ globals; allocation-free) ----------------
__device__ float g_x[NN * 64];
__device__ __nv_bfloat16 g_xh[NN * 64], g_xl[NN * 64];
__device__ __nv_bfloat16 g_ehA[NE * 64], g_elA[NE * 64];   // ping
__device__ __nv_bfloat16 g_ehB[NE * 64], g_elB[NE * 64];   // pong
__device__ float g_u[NB * 64];
__device__ __nv_bfloat16 g_uh[NB * 64], g_ul[NB * 64];
__device__ float g_agg[NN * 64];
__device__ float g_pool[NB * 64];
__device__ float g_cd[NN], g_id[NN], g_cb[NB], g_ib[NB];
__device__ float g_sums[128], g_sc[64], g_sf[64];
__device__ uint32_t g_bfrag[3 * 16384];   // per-layer mma B fragments (hi/lo interleaved)

// ---------------- helpers ----------------
__device__ __forceinline__ uint32_t smem_u32(const void* p) {
    uint32_t a;
    asm("{ .reg .u64 t; cvta.to.shared.u64 t, %1; cvt.u32.u64 %0, t; }" : "=r"(a) : "l"(p));
    return a;
}
__device__ __forceinline__ void red2(float* p, float a, float b) {
    asm volatile("red.global.add.v2.f32 [%0], {%1, %2};" :: "l"(p), "f"(a), "f"(b) : "memory");
}
__device__ __forceinline__ void ldmx4(uint32_t* r, uint32_t addr) {
    asm volatile("ldmatrix.sync.aligned.m8n8.x4.shared.b16 {%0,%1,%2,%3}, [%4];"
                 : "=r"(r[0]), "=r"(r[1]), "=r"(r[2]), "=r"(r[3]) : "r"(addr));
}
__device__ __forceinline__ void lds128(uint32_t* r, uint32_t addr) {
    asm volatile("ld.shared.v4.u32 {%0,%1,%2,%3}, [%4];"
                 : "=r"(r[0]), "=r"(r[1]), "=r"(r[2]), "=r"(r[3]) : "r"(addr));
}
__device__ __forceinline__ void mma16816(float* d, const uint32_t* a, const uint32_t* b) {
    asm volatile(
        "mma.sync.aligned.m16n8k16.row.col.f32.bf16.bf16.f32 "
        "{%0,%1,%2,%3}, {%4,%5,%6,%7}, {%8,%9}, {%0,%1,%2,%3};"
        : "+f"(d[0]), "+f"(d[1]), "+f"(d[2]), "+f"(d[3])
        : "r"(a[0]), "r"(a[1]), "r"(a[2]), "r"(a[3]), "r"(b[0]), "r"(b[1]));
}
__device__ __forceinline__ uint32_t packbf(float a, float b) {
    __nv_bfloat162 t = __floats2bfloat162_rn(a, b);
    return *reinterpret_cast<uint32_t*>(&t);
}

// ---------------- BatchNorm stats: block-reduced, 1 atomic/col/block ----------------
template <int W>
__global__ void bn_stats(const float* __restrict__ in, int rows, float* __restrict__ sums) {
    __shared__ float sh[2][8][W];
    int c = threadIdx.x, ty = threadIdx.y;
    float s = 0.f, s2 = 0.f;
    for (int r = blockIdx.x * 8 + ty; r < rows; r += gridDim.x * 8) {
        float v = in[r * W + c];
        s += v; s2 += v * v;
    }
    sh[0][ty][c] = s; sh[1][ty][c] = s2;
    __syncthreads();
    if (ty == 0) {
#pragma unroll
        for (int t = 1; t < 8; t++) { s += sh[0][t][c]; s2 += sh[1][t][c]; }
        atomicAdd(&sums[c], s);
        atomicAdd(&sums[W + c], s2);
    }
}

__global__ void bn_finalize(const float* __restrict__ sums, const float* __restrict__ gamma,
                            const float* __restrict__ beta, float inv_rows, int width,
                            float* __restrict__ scale, float* __restrict__ shift) {
    int c = threadIdx.x;
    if (c < width) {
        float mean = sums[c] * inv_rows;
        float var = sums[width + c] * inv_rows - mean * mean;
        float sc = gamma[c] * rsqrtf(var + 1e-5f);
        scale[c] = sc;
        shift[c] = beta[c] - mean * sc;
    }
}

// BN apply + bf16 hi/lo split variants
__global__ void bn_split_x(const float* __restrict__ in, const float* __restrict__ sc,
                           const float* __restrict__ sf, float* __restrict__ xf,
                           __nv_bfloat16* __restrict__ xh, __nv_bfloat16* __restrict__ xl) {
    int i = blockIdx.x * blockDim.x + threadIdx.x;
    if (i < NN * 64) {
        int c = i & 63;
        float v = fmaf(in[i], sc[c], sf[c]);
        xf[i] = v;
        __nv_bfloat16 h = __float2bfloat16(v);
        xh[i] = h;
        xl[i] = __float2bfloat16(v - __bfloat162float(h));
    }
}
__global__ void bn_split_e(const float* __restrict__ in, const float* __restrict__ sc,
                           const float* __restrict__ sf,
                           __nv_bfloat16* __restrict__ eh, __nv_bfloat16* __restrict__ el) {
    int i = blockIdx.x * blockDim.x + threadIdx.x;
    if (i < NE * 32) {
        int c = i & 31;
        float v = fmaf(in[i], sc[c], sf[c]);
        __nv_bfloat16 h = __float2bfloat16(v);
        eh[i] = h;
        el[i] = __float2bfloat16(v - __bfloat162float(h));
    }
}
__global__ void bn_split_u(const float* __restrict__ in, const float* __restrict__ sc,
                           const float* __restrict__ sf, float* __restrict__ uf,
                           __nv_bfloat16* __restrict__ uh, __nv_bfloat16* __restrict__ ul) {
    int i = blockIdx.x * blockDim.x + threadIdx.x;
    if (i < NB * 32) {
        int b = i >> 5, c = i & 31;
        float v = fmaf(in[i], sc[c], sf[c]);
        uf[b * 64 + c] = v;
        __nv_bfloat16 h = __float2bfloat16(v);
        uh[b * 64 + c] = h;
        ul[b * 64 + c] = __float2bfloat16(v - __bfloat162float(h));
    }
}
__global__ void split_x(const float* __restrict__ in, __nv_bfloat16* __restrict__ xh,
                        __nv_bfloat16* __restrict__ xl) {
    int i = blockIdx.x * blockDim.x + threadIdx.x;
    if (i < NN * 64) {
        float v = in[i];
        __nv_bfloat16 h = __float2bfloat16(v);
        xh[i] = h;
        xl[i] = __float2bfloat16(v - __bfloat162float(h));
    }
}
__global__ void split_u(const float* __restrict__ in, __nv_bfloat16* __restrict__ uh,
                        __nv_bfloat16* __restrict__ ul) {
    int i = blockIdx.x * blockDim.x + threadIdx.x;
    if (i < NB * 64) {
        float v = in[i];
        __nv_bfloat16 h = __float2bfloat16(v);
        uh[i] = h;
        ul[i] = __float2bfloat16(v - __bfloat162float(h));
    }
}

// ---- pack W [K x 64] into mma.m16n8k16 B-fragment order, hi/lo ----
// out idx = ((kt*8 + nt)*32 + lane)*4 + {hi0, hi1, lo0, lo1}
// hi0 = (B[k0][n], B[k0+1][n]); hi1 = (B[k0+8][n], B[k0+9][n]); k0 = 16kt + 2*(lane%4); n = 8nt + lane/4
__global__ void bfrag_pack(const float* __restrict__ W, int K, uint32_t* __restrict__ out) {
    int i = blockIdx.x * blockDim.x + threadIdx.x;
    int total = (K / 16) * 8 * 32;
    if (i >= total) return;
    int lane = i & 31;
    int nt = (i >> 5) & 7;
    int kt = i >> 8;
    int n = nt * 8 + (lane >> 2);
    int k0 = kt * 16 + 2 * (lane & 3);
    float v00 = W[k0 * 64 + n],       v01 = W[(k0 + 1) * 64 + n];
    float v10 = W[(k0 + 8) * 64 + n], v11 = W[(k0 + 9) * 64 + n];
    float h00 = __bfloat162float(__float2bfloat16(v00));
    float h01 = __bfloat162float(__float2bfloat16(v01));
    float h10 = __bfloat162float(__float2bfloat16(v10));
    float h11 = __bfloat162float(__float2bfloat16(v11));
    out[4 * i + 0] = packbf(v00, v01);
    out[4 * i + 1] = packbf(v10, v11);
    out[4 * i + 2] = packbf(v00 - h00, v01 - h01);
    out[4 * i + 3] = packbf(v10 - h10, v11 - h11);
}

// ---------------- counts / inverses ----------------
__global__ void count_idx(const int* __restrict__ idx, float* __restrict__ cnt, int n) {
    int i = blockIdx.x * blockDim.x + threadIdx.x;
    if (i < n) atomicAdd(&cnt[idx[i]], 1.f);
}
__global__ void make_inv(const float* __restrict__ cnt, float* __restrict__ inv, int n) {
    int i = blockIdx.x * blockDim.x + threadIdx.x;
    if (i < n) inv[i] = 1.f / fmaxf(cnt[i], 1.f);
}

// ---------------- edge MLP via mma.sync bf16-split GEMM ----------------
// Per block: M=128 edges (8 warps x 16 rows), N=64, K=DIN.
// A = [x_src|x_dst|e|u_b] gathered hi/lo into padded row-major SMEM; ldmatrix.x4.
// B = W pre-packed in fragment order (hi/lo). D = Ah*Bh + Al*Bh + Ah*Bl, fp32 acc.
// Epilogue: bias+relu, red.global.v2 into agg[dst], write bf16 hi/lo or fp32 (final).
template <int K, int EW, bool FINAL>
__global__ void __launch_bounds__(256, 1)
edge_gemm(const __nv_bfloat16* __restrict__ xh, const __nv_bfloat16* __restrict__ xl,
          const __nv_bfloat16* __restrict__ ehi, const __nv_bfloat16* __restrict__ eli,
          const __nv_bfloat16* __restrict__ uh, const __nv_bfloat16* __restrict__ ul,
          const int* __restrict__ src, const int* __restrict__ dst,
          const int* __restrict__ batch,
          const uint32_t* __restrict__ bfrag, const float* __restrict__ bias,
          float* __restrict__ e_out, __nv_bfloat16* __restrict__ eho,
          __nv_bfloat16* __restrict__ elo, float* __restrict__ agg) {
    constexpr int RU = K / 8;            // 16B chunks per row
    constexpr int NKT = K / 16;          // k-tiles
    constexpr int LDA = K * 2 + 16;      // padded row pitch (bytes), conflict-free ldmatrix
    constexpr int ASZ = 128 * LDA;       // one A tile (hi or lo)
    constexpr int SM_A = 2048;
    constexpr int SM_B = SM_A + 2 * ASZ;
    constexpr int BF_U32 = NKT * 8 * 32 * 4;

    extern __shared__ char smem[];
    float* biasS = (float*)smem;
    int* sT = (int*)(smem + 256);
    int* dT = (int*)(smem + 768);
    int* bT = (int*)(smem + 1280);
    const uint32_t sb = smem_u32(smem);

    const int tid = threadIdx.x;
    const int wid = tid >> 5;
    const int lane = tid & 31;
    const int ebase = blockIdx.x * 128;

    if (tid < 128) {
        int ee = min(ebase + tid, NE - 1);
        int s = src[ee];
        sT[tid] = s; dT[tid] = dst[ee]; bT[tid] = batch[s];
    }
    if (tid < 64) biasS[tid] = bias[tid];
    __syncthreads();

    // ---- stage A (gathered rows, hi at SM_A, lo at SM_A+ASZ) ----
    for (int it = tid; it < 128 * RU; it += 256) {
        int r = it / RU, j = it - r * RU;
        const uint4 *ph, *pl;
        if (j < 8) {
            int o = sT[r] * 8 + j;
            ph = (const uint4*)xh + o; pl = (const uint4*)xl + o;
        } else if (j < 16) {
            int o = dT[r] * 8 + (j - 8);
            ph = (const uint4*)xh + o; pl = (const uint4*)xl + o;
        } else if (j < 16 + EW / 8) {
            int ee = min(ebase + r, NE - 1);
            int o = ee * (EW / 8) + (j - 16);
            ph = (const uint4*)ehi + o; pl = (const uint4*)eli + o;
        } else {
            int o = bT[r] * 8 + (j - 16 - EW / 8);
            ph = (const uint4*)uh + o; pl = (const uint4*)ul + o;
        }
        uint32_t da = sb + SM_A + r * LDA + j * 16;
        uint4 vh = *ph, vl = *pl;
        asm volatile("st.shared.v4.b32 [%0], {%1, %2, %3, %4};" :: "r"(da),
                     "r"(vh.x), "r"(vh.y), "r"(vh.z), "r"(vh.w) : "memory");
        asm volatile("st.shared.v4.b32 [%0], {%1, %2, %3, %4};" :: "r"(da + ASZ),
                     "r"(vl.x), "r"(vl.y), "r"(vl.z), "r"(vl.w) : "memory");
    }
    // ---- stage B fragments ----
    {
        const uint4* s4 = (const uint4*)bfrag;
        uint4* d4 = (uint4*)(smem + SM_B);
        for (int i = tid; i < BF_U32 / 4; i += 256) d4[i] = s4[i];
    }
    __syncthreads();

    // ---- mma mainloop ----
    float acc[8][4];
#pragma unroll
    for (int nt = 0; nt < 8; nt++)
#pragma unroll
        for (int r = 0; r < 4; r++) acc[nt][r] = 0.f;

    const uint32_t arow = sb + SM_A + (wid * 16 + (lane & 15)) * LDA + (lane >> 4) * 16;
#pragma unroll
    for (int kt = 0; kt < NKT; kt++) {
        uint32_t Ah[4], Al[4];
        ldmx4(Ah, arow + kt * 32);
        ldmx4(Al, arow + kt * 32 + ASZ);
        const uint32_t baddr = sb + SM_B + (uint32_t)(kt * 8 * 32 + lane) * 16;
#pragma unroll
        for (int nt = 0; nt < 8; nt++) {
            uint32_t bb[4];
            lds128(bb, baddr + nt * 512);
            mma16816(acc[nt], Ah, bb);       // hi * hi
            mma16816(acc[nt], Al, bb);       // lo * hi
            mma16816(acc[nt], Ah, bb + 2);   // hi * lo
        }
    }

    // ---- epilogue ----
    const int r0 = wid * 16 + (lane >> 2);
    const int cbase = 2 * (lane & 3);
#pragma unroll
    for (int half = 0; half < 2; half++) {
        int row = r0 + 8 * half;
        int ee = ebase + row;
        if (ee < NE) {
            float* ag = agg + (size_t)dT[row] * 64 + cbase;
            if (FINAL) {
                float* eo = e_out + (size_t)ee * 64 + cbase;
#pragma unroll
                for (int nt = 0; nt < 8; nt++) {
                    int c0 = nt * 8 + cbase;
                    float v0 = fmaxf(acc[nt][2 * half] + biasS[c0], 0.f);
                    float v1 = fmaxf(acc[nt][2 * half + 1] + biasS[c0 + 1], 0.f);
                    red2(ag + nt * 8, v0, v1);
                    asm volatile("st.global.v2.f32 [%0], {%1,%2};"
                                 :: "l"(eo + nt * 8), "f"(v0), "f"(v1) : "memory");
                }
            } else {
                uint32_t* ho = (uint32_t*)eho + (size_t)ee * 32 + (lane & 3);
                uint32_t* lo = (uint32_t*)elo + (size_t)ee * 32 + (lane & 3);
#pragma unroll
                for (int nt = 0; nt < 8; nt++) {
                    int c0 = nt * 8 + cbase;
                    float v0 = fmaxf(acc[nt][2 * half] + biasS[c0], 0.f);
                    float v1 = fmaxf(acc[nt][2 * half + 1] + biasS[c0 + 1], 0.f);
                    red2(ag + nt * 8, v0, v1);
                    float h0 = __bfloat162float(__float2bfloat16(v0));
                    float h1 = __bfloat162float(__float2bfloat16(v1));
                    ho[nt * 4] = packbf(v0, v1);
                    lo[nt * 4] = packbf(v0 - h0, v1 - h1);
                }
            }
        }
    }
}

// ---------------- node MLP (warp-shuffle fp32) + fused pool atomics ----------------
template <int DIN, int UW>
__global__ void node_mlp(const float* __restrict__ x_in, const float* __restrict__ agg,
                         const float* __restrict__ inv_dst, const float* __restrict__ u,
                         const int* __restrict__ batch, const float* __restrict__ W,
                         const float* __restrict__ bias, float* __restrict__ x_out,
                         float* __restrict__ pool) {
    extern __shared__ float Wsh[];
    for (int i = threadIdx.x; i < DIN * 64; i += blockDim.x) Wsh[i] = W[i];
    __syncthreads();
    const int lane = threadIdx.x & 31;
    const int warp = threadIdx.x >> 5;
    const int nwarp = blockDim.x >> 5;
    const float b0 = bias[lane], b1 = bias[lane + 32];
    constexpr int EPW = 4;
    constexpr int NCH = DIN / 32;

    for (int nbase = (blockIdx.x * nwarp + warp) * EPW; nbase < NN;
         nbase += gridDim.x * nwarp * EPW) {
        int ns[EPW], bN[EPW];
        float rc[EPW], acc0[EPW], acc1[EPW];
#pragma unroll
        for (int i = 0; i < EPW; i++) {
            int nn = min(nbase + i, NN - 1);
            ns[i] = nn; bN[i] = batch[nn]; rc[i] = inv_dst[nn];
            acc0[i] = b0; acc1[i] = b1;
        }
#pragma unroll
        for (int c = 0; c < NCH; c++) {
            float v[EPW];
#pragma unroll
            for (int i = 0; i < EPW; i++) {
                if (c < 2)       v[i] = x_in[ns[i] * 64 + c * 32 + lane];
                else if (c < 4)  v[i] = agg[ns[i] * 64 + (c - 2) * 32 + lane] * rc[i];
                else             v[i] = u[bN[i] * 64 + (c - 4) * 32 + lane];
            }
#pragma unroll
            for (int t = 0; t < 32; t++) {
                float w0 = Wsh[(c * 32 + t) * 64 + lane];
                float w1 = Wsh[(c * 32 + t) * 64 + 32 + lane];
#pragma unroll
                for (int i = 0; i < EPW; i++) {
                    float s = __shfl_sync(0xffffffffu, v[i], t);
                    acc0[i] = fmaf(s, w0, acc0[i]);
                    acc1[i] = fmaf(s, w1, acc1[i]);
                }
            }
        }
#pragma unroll
        for (int i = 0; i < EPW; i++) {
            if (nbase + i < NN) {
                float v0 = fmaxf(acc0[i], 0.f), v1 = fmaxf(acc1[i], 0.f);
                x_out[ns[i] * 64 + lane] = v0;
                x_out[ns[i] * 64 + 32 + lane] = v1;
                atomicAdd(&pool[bN[i] * 64 + lane], v0);
                atomicAdd(&pool[bN[i] * 64 + 32 + lane], v1);
            }
        }
    }
}

// ---------------- global MLP ----------------
template <int UW>
__global__ void glob_mlp(const float* __restrict__ xpool, const float* __restrict__ invb,
                         const float* __restrict__ u_in, const float* __restrict__ W,
                         const float* __restrict__ bias, float* __restrict__ u_out) {
    __shared__ float us[64];
    __shared__ float ps[64];
    int b = blockIdx.x;
    int h = threadIdx.x;
    if (h < UW) us[h] = u_in[b * 64 + h];
    ps[h] = xpool[b * 64 + h] * invb[b];
    __syncthreads();
    float acc = bias[h];
#pragma unroll 8
    for (int d = 0; d < 64; d++) acc = fmaf(ps[d], W[d * 64 + h], acc);
#pragma unroll 8
    for (int d = 0; d < UW; d++) acc = fmaf(us[d], W[(64 + d) * 64 + h], acc);
    u_out[b * 64 + h] = fmaxf(acc, 0.f);
}

// ---------------- host orchestration ----------------
extern "C" void kernel_launch(void* const* d_in, const int* in_sizes, int n_in,
                              void* d_out, int out_size) {
    const float* x     = (const float*)d_in[0];
    const int*   eidx  = (const int*)d_in[1];
    const float* e     = (const float*)d_in[2];
    const float* u     = (const float*)d_in[3];
    const int*   batch = (const int*)d_in[4];
    const float* gn = (const float*)d_in[5],  *bnb = (const float*)d_in[6];
    const float* ge = (const float*)d_in[7],  *beb = (const float*)d_in[8];
    const float* gg = (const float*)d_in[9],  *bgb = (const float*)d_in[10];
    const float* We[3] = {(const float*)d_in[11], (const float*)d_in[17], (const float*)d_in[23]};
    const float* be[3] = {(const float*)d_in[12], (const float*)d_in[18], (const float*)d_in[24]};
    const float* Wn[3] = {(const float*)d_in[13], (const float*)d_in[19], (const float*)d_in[25]};
    const float* bn[3] = {(const float*)d_in[14], (const float*)d_in[20], (const float*)d_in[26]};
    const float* Wg[3] = {(const float*)d_in[15], (const float*)d_in[21], (const float*)d_in[27]};
    const float* bg[3] = {(const float*)d_in[16], (const float*)d_in[22], (const float*)d_in[28]};

    const int* src = eidx;
    const int* dst = eidx + NE;

    float* out_x = (float*)d_out;
    float* out_e = out_x + (size_t)NN * 64;
    float* out_u = out_e + (size_t)NE * 64;

    float *p_x, *p_u, *p_agg, *p_pool, *p_cd, *p_cb, *p_id, *p_ib, *p_sums, *p_sc, *p_sf;
    __nv_bfloat16 *p_xh, *p_xl, *p_ehA, *p_elA, *p_ehB, *p_elB, *p_uh, *p_ul;
    uint32_t* p_bf;
    cudaGetSymbolAddress((void**)&p_x, g_x);
    cudaGetSymbolAddress((void**)&p_u, g_u);
    cudaGetSymbolAddress((void**)&p_agg, g_agg);
    cudaGetSymbolAddress((void**)&p_pool, g_pool);
    cudaGetSymbolAddress((void**)&p_cd, g_cd);
    cudaGetSymbolAddress((void**)&p_cb, g_cb);
    cudaGetSymbolAddress((void**)&p_id, g_id);
    cudaGetSymbolAddress((void**)&p_ib, g_ib);
    cudaGetSymbolAddress((void**)&p_sums, g_sums);
    cudaGetSymbolAddress((void**)&p_sc, g_sc);
    cudaGetSymbolAddress((void**)&p_sf, g_sf);
    cudaGetSymbolAddress((void**)&p_xh, g_xh);
    cudaGetSymbolAddress((void**)&p_xl, g_xl);
    cudaGetSymbolAddress((void**)&p_ehA, g_ehA);
    cudaGetSymbolAddress((void**)&p_elA, g_elA);
    cudaGetSymbolAddress((void**)&p_ehB, g_ehB);
    cudaGetSymbolAddress((void**)&p_elB, g_elB);
    cudaGetSymbolAddress((void**)&p_uh, g_uh);
    cudaGetSymbolAddress((void**)&p_ul, g_ul);
    cudaGetSymbolAddress((void**)&p_bf, g_bfrag);

    // SMEM budgets: 2048 hdr + 2*A + Bfrag
    const int SM192 = 2048 + 2 * (128 * (192 * 2 + 16)) + (192 / 16) * 8 * 32 * 16;  // 155648
    const int SM256 = 2048 + 2 * (128 * (256 * 2 + 16)) + (256 / 16) * 8 * 32 * 16;  // 202752
    cudaFuncSetAttribute(edge_gemm<192, 32, false>, cudaFuncAttributeMaxDynamicSharedMemorySize, SM192);
    cudaFuncSetAttribute(edge_gemm<256, 64, false>, cudaFuncAttributeMaxDynamicSharedMemorySize, SM256);
    cudaFuncSetAttribute(edge_gemm<256, 64, true>,  cudaFuncAttributeMaxDynamicSharedMemorySize, SM256);
    cudaFuncSetAttribute(node_mlp<160, 32>, cudaFuncAttributeMaxDynamicSharedMemorySize, 160 * 64 * 4);
    cudaFuncSetAttribute(node_mlp<192, 64>, cudaFuncAttributeMaxDynamicSharedMemorySize, 192 * 64 * 4);

    // ---- input BatchNorms + splits ----
    cudaMemsetAsync(p_sums, 0, 128 * sizeof(float));
    bn_stats<64><<<296, dim3(64, 8)>>>(x, NN, p_sums);
    bn_finalize<<<1, 64>>>(p_sums, gn, bnb, 1.f / NN, 64, p_sc, p_sf);
    bn_split_x<<<(NN * 64 + 255) / 256, 256>>>(x, p_sc, p_sf, p_x, p_xh, p_xl);

    cudaMemsetAsync(p_sums, 0, 128 * sizeof(float));
    bn_stats<32><<<592, dim3(32, 8)>>>(e, NE, p_sums);
    bn_finalize<<<1, 64>>>(p_sums, ge, beb, 1.f / NE, 32, p_sc, p_sf);
    bn_split_e<<<(NE * 32 + 255) / 256, 256>>>(e, p_sc, p_sf, p_ehA, p_elA);

    cudaMemsetAsync(p_sums, 0, 128 * sizeof(float));
    bn_stats<32><<<2, dim3(32, 8)>>>(u, NB, p_sums);
    bn_finalize<<<1, 64>>>(p_sums, gg, bgb, 1.f / NB, 32, p_sc, p_sf);
    bn_split_u<<<(NB * 32 + 63) / 64, 64>>>(u, p_sc, p_sf, p_u, p_uh, p_ul);

    // ---- segment counts ----
    cudaMemsetAsync(p_cd, 0, NN * sizeof(float));
    cudaMemsetAsync(p_cb, 0, NB * sizeof(float));
    count_idx<<<(NE + 255) / 256, 256>>>(dst, p_cd, NE);
    count_idx<<<(NN + 255) / 256, 256>>>(batch, p_cb, NN);
    make_inv<<<(NN + 255) / 256, 256>>>(p_cd, p_id, NN);
    make_inv<<<1, 64>>>(p_cb, p_ib, NB);

    // ---- pack edge weights into mma B-fragment order (hi/lo) ----
    bfrag_pack<<<(12 * 256 + 255) / 256, 256>>>(We[0], 192, p_bf + 0 * 16384);
    bfrag_pack<<<(16 * 256 + 255) / 256, 256>>>(We[1], 256, p_bf + 1 * 16384);
    bfrag_pack<<<(16 * 256 + 255) / 256, 256>>>(We[2], 256, p_bf + 2 * 16384);

    const int EGRID = (NE + 127) / 128;
    const int NGRID = 938;

    // ---- layer 0 ----
    cudaMemsetAsync(p_agg, 0, (size_t)NN * 64 * sizeof(float));
    edge_gemm<192, 32, false><<<EGRID, 256, SM192>>>(
        p_xh, p_xl, p_ehA, p_elA, p_uh, p_ul, src, dst, batch,
        p_bf + 0 * 16384, be[0], nullptr, p_ehB, p_elB, p_agg);
    cudaMemsetAsync(p_pool, 0, NB * 64 * sizeof(float));
    node_mlp<160, 32><<<NGRID, 256, 160 * 64 * 4>>>(p_x, p_agg, p_id, p_u, batch, Wn[0], bn[0], p_x, p_pool);
    glob_mlp<32><<<NB, 64>>>(p_pool, p_ib, p_u, Wg[0], bg[0], p_u);
    split_x<<<(NN * 64 + 255) / 256, 256>>>(p_x, p_xh, p_xl);
    split_u<<<(NB * 64 + 63) / 64, 64>>>(p_u, p_uh, p_ul);

    // ---- layer 1 ----
    cudaMemsetAsync(p_agg, 0, (size_t)NN * 64 * sizeof(float));
    edge_gemm<256, 64, false><<<EGRID, 256, SM256>>>(
        p_xh, p_xl, p_ehB, p_elB, p_uh, p_ul, src, dst, batch,
        p_bf + 1 * 16384, be[1], nullptr, p_ehA, p_elA, p_agg);
    cudaMemsetAsync(p_pool, 0, NB * 64 * sizeof(float));
    node_mlp<192, 64><<<NGRID, 256, 192 * 64 * 4>>>(p_x, p_agg, p_id, p_u, batch, Wn[1], bn[1], p_x, p_pool);
    glob_mlp<64><<<NB, 64>>>(p_pool, p_ib, p_u, Wg[1], bg[1], p_u);
    split_x<<<(NN * 64 + 255) / 256, 256>>>(p_x, p_xh, p_xl);
    split_u<<<(NB * 64 + 63) / 64, 64>>>(p_u, p_uh, p_ul);

    // ---- layer 2 (final: write out_e / out_x / out_u) ----
    cudaMemsetAsync(p_agg, 0, (size_t)NN * 64 * sizeof(float));
    edge_gemm<256, 64, true><<<EGRID, 256, SM256>>>(
        p_xh, p_xl, p_ehA, p_elA, p_uh, p_ul, src, dst, batch,
        p_bf + 2 * 16384, be[2], out_e, p_ehB, p_elB, p_agg);
    cudaMemsetAsync(p_pool, 0, NB * 64 * sizeof(float));
    node_mlp<192, 64><<<NGRID, 256, 192 * 64 * 4>>>(p_x, p_agg, p_id, p_u, batch, Wn[2], bn[2], out_x, p_pool);
    glob_mlp<64><<<NB, 64>>>(p_pool, p_ib, p_u, Wg[2], bg[2], out_u);
}

// round 6
// speedup vs baseline: 1.0132x; 1.0132x over previous
#include <cuda_runtime.h>
#include <cuda_bf16.h>
#include <cstdint>

#define NN 30000
#define NE 300000
#define NB 64

// ---------------- scratch (__device__ globals; allocation-free) ----------------
__device__ float g_x[NN * 64];
__device__ __nv_bfloat16 g_xh[NN * 64], g_xl[NN * 64];
__device__ __nv_bfloat16 g_ehA[NE * 64], g_elA[NE * 64];   // ping
__device__ __nv_bfloat16 g_ehB[NE * 64], g_elB[NE * 64];   // pong
__device__ float g_u[NB * 64];
__device__ __nv_bfloat16 g_uh[NB * 64], g_ul[NB * 64];
__device__ float g_agg[NN * 64];
__device__ float g_pool[NB * 64];
__device__ float g_cd[NN], g_id[NN], g_cb[NB], g_ib[NB];
__device__ float g_sums[128], g_sc[64], g_sf[64];
__device__ uint32_t g_bfrag[3 * 16384];   // per-layer mma B fragments (hi/lo interleaved)

// ---------------- helpers ----------------
__device__ __forceinline__ uint32_t smem_u32(const void* p) {
    uint32_t a;
    asm("{ .reg .u64 t; cvta.to.shared.u64 t, %1; cvt.u32.u64 %0, t; }" : "=r"(a) : "l"(p));
    return a;
}
__device__ __forceinline__ void red2(float* p, float a, float b) {
    asm volatile("red.global.add.v2.f32 [%0], {%1, %2};" :: "l"(p), "f"(a), "f"(b) : "memory");
}
__device__ __forceinline__ void ldmx4(uint32_t* r, uint32_t addr) {
    asm volatile("ldmatrix.sync.aligned.m8n8.x4.shared.b16 {%0,%1,%2,%3}, [%4];"
                 : "=r"(r[0]), "=r"(r[1]), "=r"(r[2]), "=r"(r[3]) : "r"(addr));
}
__device__ __forceinline__ void lds128(uint32_t* r, uint32_t addr) {
    asm volatile("ld.shared.v4.u32 {%0,%1,%2,%3}, [%4];"
                 : "=r"(r[0]), "=r"(r[1]), "=r"(r[2]), "=r"(r[3]) : "r"(addr));
}
__device__ __forceinline__ void mma16816(float* d, const uint32_t* a, const uint32_t* b) {
    asm volatile(
        "mma.sync.aligned.m16n8k16.row.col.f32.bf16.bf16.f32 "
        "{%0,%1,%2,%3}, {%4,%5,%6,%7}, {%8,%9}, {%0,%1,%2,%3};"
        : "+f"(d[0]), "+f"(d[1]), "+f"(d[2]), "+f"(d[3])
        : "r"(a[0]), "r"(a[1]), "r"(a[2]), "r"(a[3]), "r"(b[0]), "r"(b[1]));
}
__device__ __forceinline__ uint32_t packbf(float a, float b) {
    __nv_bfloat162 t = __floats2bfloat162_rn(a, b);
    return *reinterpret_cast<uint32_t*>(&t);
}

// ---------------- BatchNorm stats: block-reduced, 1 atomic/col/block ----------------
template <int W>
__global__ void bn_stats(const float* __restrict__ in, int rows, float* __restrict__ sums) {
    __shared__ float sh[2][8][W];
    int c = threadIdx.x, ty = threadIdx.y;
    float s = 0.f, s2 = 0.f;
    for (int r = blockIdx.x * 8 + ty; r < rows; r += gridDim.x * 8) {
        float v = in[r * W + c];
        s += v; s2 += v * v;
    }
    sh[0][ty][c] = s; sh[1][ty][c] = s2;
    __syncthreads();
    if (ty == 0) {
#pragma unroll
        for (int t = 1; t < 8; t++) { s += sh[0][t][c]; s2 += sh[1][t][c]; }
        atomicAdd(&sums[c], s);
        atomicAdd(&sums[W + c], s2);
    }
}

__global__ void bn_finalize(const float* __restrict__ sums, const float* __restrict__ gamma,
                            const float* __restrict__ beta, float inv_rows, int width,
                            float* __restrict__ scale, float* __restrict__ shift) {
    int c = threadIdx.x;
    if (c < width) {
        float mean = sums[c] * inv_rows;
        float var = sums[width + c] * inv_rows - mean * mean;
        float sc = gamma[c] * rsqrtf(var + 1e-5f);
        scale[c] = sc;
        shift[c] = beta[c] - mean * sc;
    }
}

// BN apply + bf16 hi/lo split variants
__global__ void bn_split_x(const float* __restrict__ in, const float* __restrict__ sc,
                           const float* __restrict__ sf, float* __restrict__ xf,
                           __nv_bfloat16* __restrict__ xh, __nv_bfloat16* __restrict__ xl) {
    int i = blockIdx.x * blockDim.x + threadIdx.x;
    if (i < NN * 64) {
        int c = i & 63;
        float v = fmaf(in[i], sc[c], sf[c]);
        xf[i] = v;
        __nv_bfloat16 h = __float2bfloat16(v);
        xh[i] = h;
        xl[i] = __float2bfloat16(v - __bfloat162float(h));
    }
}
__global__ void bn_split_e(const float* __restrict__ in, const float* __restrict__ sc,
                           const float* __restrict__ sf,
                           __nv_bfloat16* __restrict__ eh, __nv_bfloat16* __restrict__ el) {
    int i = blockIdx.x * blockDim.x + threadIdx.x;
    if (i < NE * 32) {
        int c = i & 31;
        float v = fmaf(in[i], sc[c], sf[c]);
        __nv_bfloat16 h = __float2bfloat16(v);
        eh[i] = h;
        el[i] = __float2bfloat16(v - __bfloat162float(h));
    }
}
__global__ void bn_split_u(const float* __restrict__ in, const float* __restrict__ sc,
                           const float* __restrict__ sf, float* __restrict__ uf,
                           __nv_bfloat16* __restrict__ uh, __nv_bfloat16* __restrict__ ul) {
    int i = blockIdx.x * blockDim.x + threadIdx.x;
    if (i < NB * 32) {
        int b = i >> 5, c = i & 31;
        float v = fmaf(in[i], sc[c], sf[c]);
        uf[b * 64 + c] = v;
        __nv_bfloat16 h = __float2bfloat16(v);
        uh[b * 64 + c] = h;
        ul[b * 64 + c] = __float2bfloat16(v - __bfloat162float(h));
    }
}
__global__ void split_x(const float* __restrict__ in, __nv_bfloat16* __restrict__ xh,
                        __nv_bfloat16* __restrict__ xl) {
    int i = blockIdx.x * blockDim.x + threadIdx.x;
    if (i < NN * 64) {
        float v = in[i];
        __nv_bfloat16 h = __float2bfloat16(v);
        xh[i] = h;
        xl[i] = __float2bfloat16(v - __bfloat162float(h));
    }
}
__global__ void split_u(const float* __restrict__ in, __nv_bfloat16* __restrict__ uh,
                        __nv_bfloat16* __restrict__ ul) {
    int i = blockIdx.x * blockDim.x + threadIdx.x;
    if (i < NB * 64) {
        float v = in[i];
        __nv_bfloat16 h = __float2bfloat16(v);
        uh[i] = h;
        ul[i] = __float2bfloat16(v - __bfloat162float(h));
    }
}

// ---- pack W [K x 64] into mma.m16n8k16 B-fragment order, hi/lo ----
// out idx = ((kt*8 + nt)*32 + lane)*4 + {hi0, hi1, lo0, lo1}
// hi0 = (B[k0][n], B[k0+1][n]); hi1 = (B[k0+8][n], B[k0+9][n]); k0 = 16kt + 2*(lane%4); n = 8nt + lane/4
__global__ void bfrag_pack(const float* __restrict__ W, int K, uint32_t* __restrict__ out) {
    int i = blockIdx.x * blockDim.x + threadIdx.x;
    int total = (K / 16) * 8 * 32;
    if (i >= total) return;
    int lane = i & 31;
    int nt = (i >> 5) & 7;
    int kt = i >> 8;
    int n = nt * 8 + (lane >> 2);
    int k0 = kt * 16 + 2 * (lane & 3);
    float v00 = W[k0 * 64 + n],       v01 = W[(k0 + 1) * 64 + n];
    float v10 = W[(k0 + 8) * 64 + n], v11 = W[(k0 + 9) * 64 + n];
    float h00 = __bfloat162float(__float2bfloat16(v00));
    float h01 = __bfloat162float(__float2bfloat16(v01));
    float h10 = __bfloat162float(__float2bfloat16(v10));
    float h11 = __bfloat162float(__float2bfloat16(v11));
    out[4 * i + 0] = packbf(v00, v01);
    out[4 * i + 1] = packbf(v10, v11);
    out[4 * i + 2] = packbf(v00 - h00, v01 - h01);
    out[4 * i + 3] = packbf(v10 - h10, v11 - h11);
}

// ---------------- counts / inverses ----------------
__global__ void count_idx(const int* __restrict__ idx, float* __restrict__ cnt, int n) {
    int i = blockIdx.x * blockDim.x + threadIdx.x;
    if (i < n) atomicAdd(&cnt[idx[i]], 1.f);
}
__global__ void make_inv(const float* __restrict__ cnt, float* __restrict__ inv, int n) {
    int i = blockIdx.x * blockDim.x + threadIdx.x;
    if (i < n) inv[i] = 1.f / fmaxf(cnt[i], 1.f);
}

// ---------------- edge MLP via mma.sync bf16-split GEMM ----------------
// Per block: M=128 edges (8 warps x 16 rows), N=64, K=DIN.
// A = [x_src|x_dst|e|u_b] gathered hi/lo into padded row-major SMEM; ldmatrix.x4.
// B = W pre-packed in fragment order (hi/lo). D = Ah*Bh + Al*Bh + Ah*Bl, fp32 acc.
// Epilogue: bias+relu, red.global.v2 into agg[dst], write bf16 hi/lo or fp32 (final).
template <int K, int EW, bool FINAL>
__global__ void __launch_bounds__(256, 1)
edge_gemm(const __nv_bfloat16* __restrict__ xh, const __nv_bfloat16* __restrict__ xl,
          const __nv_bfloat16* __restrict__ ehi, const __nv_bfloat16* __restrict__ eli,
          const __nv_bfloat16* __restrict__ uh, const __nv_bfloat16* __restrict__ ul,
          const int* __restrict__ src, const int* __restrict__ dst,
          const int* __restrict__ batch,
          const uint32_t* __restrict__ bfrag, const float* __restrict__ bias,
          float* __restrict__ e_out, __nv_bfloat16* __restrict__ eho,
          __nv_bfloat16* __restrict__ elo, float* __restrict__ agg) {
    constexpr int RU = K / 8;            // 16B chunks per row
    constexpr int NKT = K / 16;          // k-tiles
    constexpr int LDA = K * 2 + 16;      // padded row pitch (bytes), conflict-free ldmatrix
    constexpr int ASZ = 128 * LDA;       // one A tile (hi or lo)
    constexpr int SM_A = 2048;
    constexpr int SM_B = SM_A + 2 * ASZ;
    constexpr int BF_U32 = NKT * 8 * 32 * 4;

    extern __shared__ char smem[];
    float* biasS = (float*)smem;
    int* sT = (int*)(smem + 256);
    int* dT = (int*)(smem + 768);
    int* bT = (int*)(smem + 1280);
    const uint32_t sb = smem_u32(smem);

    const int tid = threadIdx.x;
    const int wid = tid >> 5;
    const int lane = tid & 31;
    const int ebase = blockIdx.x * 128;

    if (tid < 128) {
        int ee = min(ebase + tid, NE - 1);
        int s = src[ee];
        sT[tid] = s; dT[tid] = dst[ee]; bT[tid] = batch[s];
    }
    if (tid < 64) biasS[tid] = bias[tid];
    __syncthreads();

    // ---- stage A (gathered rows, hi at SM_A, lo at SM_A+ASZ) ----
    for (int it = tid; it < 128 * RU; it += 256) {
        int r = it / RU, j = it - r * RU;
        const uint4 *ph, *pl;
        if (j < 8) {
            int o = sT[r] * 8 + j;
            ph = (const uint4*)xh + o; pl = (const uint4*)xl + o;
        } else if (j < 16) {
            int o = dT[r] * 8 + (j - 8);
            ph = (const uint4*)xh + o; pl = (const uint4*)xl + o;
        } else if (j < 16 + EW / 8) {
            int ee = min(ebase + r, NE - 1);
            int o = ee * (EW / 8) + (j - 16);
            ph = (const uint4*)ehi + o; pl = (const uint4*)eli + o;
        } else {
            int o = bT[r] * 8 + (j - 16 - EW / 8);
            ph = (const uint4*)uh + o; pl = (const uint4*)ul + o;
        }
        uint32_t da = sb + SM_A + r * LDA + j * 16;
        uint4 vh = *ph, vl = *pl;
        asm volatile("st.shared.v4.b32 [%0], {%1, %2, %3, %4};" :: "r"(da),
                     "r"(vh.x), "r"(vh.y), "r"(vh.z), "r"(vh.w) : "memory");
        asm volatile("st.shared.v4.b32 [%0], {%1, %2, %3, %4};" :: "r"(da + ASZ),
                     "r"(vl.x), "r"(vl.y), "r"(vl.z), "r"(vl.w) : "memory");
    }
    // ---- stage B fragments ----
    {
        const uint4* s4 = (const uint4*)bfrag;
        uint4* d4 = (uint4*)(smem + SM_B);
        for (int i = tid; i < BF_U32 / 4; i += 256) d4[i] = s4[i];
    }
    __syncthreads();

    // ---- mma mainloop ----
    float acc[8][4];
#pragma unroll
    for (int nt = 0; nt < 8; nt++)
#pragma unroll
        for (int r = 0; r < 4; r++) acc[nt][r] = 0.f;

    const uint32_t arow = sb + SM_A + (wid * 16 + (lane & 15)) * LDA + (lane >> 4) * 16;
#pragma unroll
    for (int kt = 0; kt < NKT; kt++) {
        uint32_t Ah[4], Al[4];
        ldmx4(Ah, arow + kt * 32);
        ldmx4(Al, arow + kt * 32 + ASZ);
        const uint32_t baddr = sb + SM_B + (uint32_t)(kt * 8 * 32 + lane) * 16;
#pragma unroll
        for (int nt = 0; nt < 8; nt++) {
            uint32_t bb[4];
            lds128(bb, baddr + nt * 512);
            mma16816(acc[nt], Ah, bb);       // hi * hi
            mma16816(acc[nt], Al, bb);       // lo * hi
            mma16816(acc[nt], Ah, bb + 2);   // hi * lo
        }
    }

    // ---- epilogue ----
    const int r0 = wid * 16 + (lane >> 2);
    const int cbase = 2 * (lane & 3);
#pragma unroll
    for (int half = 0; half < 2; half++) {
        int row = r0 + 8 * half;
        int ee = ebase + row;
        if (ee < NE) {
            float* ag = agg + (size_t)dT[row] * 64 + cbase;
            if (FINAL) {
                float* eo = e_out + (size_t)ee * 64 + cbase;
#pragma unroll
                for (int nt = 0; nt < 8; nt++) {
                    int c0 = nt * 8 + cbase;
                    float v0 = fmaxf(acc[nt][2 * half] + biasS[c0], 0.f);
                    float v1 = fmaxf(acc[nt][2 * half + 1] + biasS[c0 + 1], 0.f);
                    red2(ag + nt * 8, v0, v1);
                    asm volatile("st.global.v2.f32 [%0], {%1,%2};"
                                 :: "l"(eo + nt * 8), "f"(v0), "f"(v1) : "memory");
                }
            } else {
                uint32_t* ho = (uint32_t*)eho + (size_t)ee * 32 + (lane & 3);
                uint32_t* lo = (uint32_t*)elo + (size_t)ee * 32 + (lane & 3);
#pragma unroll
                for (int nt = 0; nt < 8; nt++) {
                    int c0 = nt * 8 + cbase;
                    float v0 = fmaxf(acc[nt][2 * half] + biasS[c0], 0.f);
                    float v1 = fmaxf(acc[nt][2 * half + 1] + biasS[c0 + 1], 0.f);
                    red2(ag + nt * 8, v0, v1);
                    float h0 = __bfloat162float(__float2bfloat16(v0));
                    float h1 = __bfloat162float(__float2bfloat16(v1));
                    ho[nt * 4] = packbf(v0, v1);
                    lo[nt * 4] = packbf(v0 - h0, v1 - h1);
                }
            }
        }
    }
}

// ---------------- node MLP (warp-shuffle fp32) + fused pool atomics ----------------
template <int DIN, int UW>
__global__ void node_mlp(const float* __restrict__ x_in, const float* __restrict__ agg,
                         const float* __restrict__ inv_dst, const float* __restrict__ u,
                         const int* __restrict__ batch, const float* __restrict__ W,
                         const float* __restrict__ bias, float* __restrict__ x_out,
                         float* __restrict__ pool) {
    extern __shared__ float Wsh[];
    for (int i = threadIdx.x; i < DIN * 64; i += blockDim.x) Wsh[i] = W[i];
    __syncthreads();
    const int lane = threadIdx.x & 31;
    const int warp = threadIdx.x >> 5;
    const int nwarp = blockDim.x >> 5;
    const float b0 = bias[lane], b1 = bias[lane + 32];
    constexpr int EPW = 4;
    constexpr int NCH = DIN / 32;

    for (int nbase = (blockIdx.x * nwarp + warp) * EPW; nbase < NN;
         nbase += gridDim.x * nwarp * EPW) {
        int ns[EPW], bN[EPW];
        float rc[EPW], acc0[EPW], acc1[EPW];
#pragma unroll
        for (int i = 0; i < EPW; i++) {
            int nn = min(nbase + i, NN - 1);
            ns[i] = nn; bN[i] = batch[nn]; rc[i] = inv_dst[nn];
            acc0[i] = b0; acc1[i] = b1;
        }
#pragma unroll
        for (int c = 0; c < NCH; c++) {
            float v[EPW];
#pragma unroll
            for (int i = 0; i < EPW; i++) {
                if (c < 2)       v[i] = x_in[ns[i] * 64 + c * 32 + lane];
                else if (c < 4)  v[i] = agg[ns[i] * 64 + (c - 2) * 32 + lane] * rc[i];
                else             v[i] = u[bN[i] * 64 + (c - 4) * 32 + lane];
            }
#pragma unroll
            for (int t = 0; t < 32; t++) {
                float w0 = Wsh[(c * 32 + t) * 64 + lane];
                float w1 = Wsh[(c * 32 + t) * 64 + 32 + lane];
#pragma unroll
                for (int i = 0; i < EPW; i++) {
                    float s = __shfl_sync(0xffffffffu, v[i], t);
                    acc0[i] = fmaf(s, w0, acc0[i]);
                    acc1[i] = fmaf(s, w1, acc1[i]);
                }
            }
        }
#pragma unroll
        for (int i = 0; i < EPW; i++) {
            if (nbase + i < NN) {
                float v0 = fmaxf(acc0[i], 0.f), v1 = fmaxf(acc1[i], 0.f);
                x_out[ns[i] * 64 + lane] = v0;
                x_out[ns[i] * 64 + 32 + lane] = v1;
                atomicAdd(&pool[bN[i] * 64 + lane], v0);
                atomicAdd(&pool[bN[i] * 64 + 32 + lane], v1);
            }
        }
    }
}

// ---------------- global MLP ----------------
template <int UW>
__global__ void glob_mlp(const float* __restrict__ xpool, const float* __restrict__ invb,
                         const float* __restrict__ u_in, const float* __restrict__ W,
                         const float* __restrict__ bias, float* __restrict__ u_out) {
    __shared__ float us[64];
    __shared__ float ps[64];
    int b = blockIdx.x;
    int h = threadIdx.x;
    if (h < UW) us[h] = u_in[b * 64 + h];
    ps[h] = xpool[b * 64 + h] * invb[b];
    __syncthreads();
    float acc = bias[h];
#pragma unroll 8
    for (int d = 0; d < 64; d++) acc = fmaf(ps[d], W[d * 64 + h], acc);
#pragma unroll 8
    for (int d = 0; d < UW; d++) acc = fmaf(us[d], W[(64 + d) * 64 + h], acc);
    u_out[b * 64 + h] = fmaxf(acc, 0.f);
}

// ---------------- host orchestration ----------------
extern "C" void kernel_launch(void* const* d_in, const int* in_sizes, int n_in,
                              void* d_out, int out_size) {
    const float* x     = (const float*)d_in[0];
    const int*   eidx  = (const int*)d_in[1];
    const float* e     = (const float*)d_in[2];
    const float* u     = (const float*)d_in[3];
    const int*   batch = (const int*)d_in[4];
    const float* gn = (const float*)d_in[5],  *bnb = (const float*)d_in[6];
    const float* ge = (const float*)d_in[7],  *beb = (const float*)d_in[8];
    const float* gg = (const float*)d_in[9],  *bgb = (const float*)d_in[10];
    const float* We[3] = {(const float*)d_in[11], (const float*)d_in[17], (const float*)d_in[23]};
    const float* be[3] = {(const float*)d_in[12], (const float*)d_in[18], (const float*)d_in[24]};
    const float* Wn[3] = {(const float*)d_in[13], (const float*)d_in[19], (const float*)d_in[25]};
    const float* bn[3] = {(const float*)d_in[14], (const float*)d_in[20], (const float*)d_in[26]};
    const float* Wg[3] = {(const float*)d_in[15], (const float*)d_in[21], (const float*)d_in[27]};
    const float* bg[3] = {(const float*)d_in[16], (const float*)d_in[22], (const float*)d_in[28]};

    const int* src = eidx;
    const int* dst = eidx + NE;

    float* out_x = (float*)d_out;
    float* out_e = out_x + (size_t)NN * 64;
    float* out_u = out_e + (size_t)NE * 64;

    float *p_x, *p_u, *p_agg, *p_pool, *p_cd, *p_cb, *p_id, *p_ib, *p_sums, *p_sc, *p_sf;
    __nv_bfloat16 *p_xh, *p_xl, *p_ehA, *p_elA, *p_ehB, *p_elB, *p_uh, *p_ul;
    uint32_t* p_bf;
    cudaGetSymbolAddress((void**)&p_x, g_x);
    cudaGetSymbolAddress((void**)&p_u, g_u);
    cudaGetSymbolAddress((void**)&p_agg, g_agg);
    cudaGetSymbolAddress((void**)&p_pool, g_pool);
    cudaGetSymbolAddress((void**)&p_cd, g_cd);
    cudaGetSymbolAddress((void**)&p_cb, g_cb);
    cudaGetSymbolAddress((void**)&p_id, g_id);
    cudaGetSymbolAddress((void**)&p_ib, g_ib);
    cudaGetSymbolAddress((void**)&p_sums, g_sums);
    cudaGetSymbolAddress((void**)&p_sc, g_sc);
    cudaGetSymbolAddress((void**)&p_sf, g_sf);
    cudaGetSymbolAddress((void**)&p_xh, g_xh);
    cudaGetSymbolAddress((void**)&p_xl, g_xl);
    cudaGetSymbolAddress((void**)&p_ehA, g_ehA);
    cudaGetSymbolAddress((void**)&p_elA, g_elA);
    cudaGetSymbolAddress((void**)&p_ehB, g_ehB);
    cudaGetSymbolAddress((void**)&p_elB, g_elB);
    cudaGetSymbolAddress((void**)&p_uh, g_uh);
    cudaGetSymbolAddress((void**)&p_ul, g_ul);
    cudaGetSymbolAddress((void**)&p_bf, g_bfrag);

    // SMEM budgets: 2048 hdr + 2*A + Bfrag
    const int SM192 = 2048 + 2 * (128 * (192 * 2 + 16)) + (192 / 16) * 8 * 32 * 16;  // 155648
    const int SM256 = 2048 + 2 * (128 * (256 * 2 + 16)) + (256 / 16) * 8 * 32 * 16;  // 202752
    cudaFuncSetAttribute(edge_gemm<192, 32, false>, cudaFuncAttributeMaxDynamicSharedMemorySize, SM192);
    cudaFuncSetAttribute(edge_gemm<256, 64, false>, cudaFuncAttributeMaxDynamicSharedMemorySize, SM256);
    cudaFuncSetAttribute(edge_gemm<256, 64, true>,  cudaFuncAttributeMaxDynamicSharedMemorySize, SM256);
    cudaFuncSetAttribute(node_mlp<160, 32>, cudaFuncAttributeMaxDynamicSharedMemorySize, 160 * 64 * 4);
    cudaFuncSetAttribute(node_mlp<192, 64>, cudaFuncAttributeMaxDynamicSharedMemorySize, 192 * 64 * 4);

    // ---- input BatchNorms + splits ----
    cudaMemsetAsync(p_sums, 0, 128 * sizeof(float));
    bn_stats<64><<<296, dim3(64, 8)>>>(x, NN, p_sums);
    bn_finalize<<<1, 64>>>(p_sums, gn, bnb, 1.f / NN, 64, p_sc, p_sf);
    bn_split_x<<<(NN * 64 + 255) / 256, 256>>>(x, p_sc, p_sf, p_x, p_xh, p_xl);

    cudaMemsetAsync(p_sums, 0, 128 * sizeof(float));
    bn_stats<32><<<592, dim3(32, 8)>>>(e, NE, p_sums);
    bn_finalize<<<1, 64>>>(p_sums, ge, beb, 1.f / NE, 32, p_sc, p_sf);
    bn_split_e<<<(NE * 32 + 255) / 256, 256>>>(e, p_sc, p_sf, p_ehA, p_elA);

    cudaMemsetAsync(p_sums, 0, 128 * sizeof(float));
    bn_stats<32><<<2, dim3(32, 8)>>>(u, NB, p_sums);
    bn_finalize<<<1, 64>>>(p_sums, gg, bgb, 1.f / NB, 32, p_sc, p_sf);
    bn_split_u<<<(NB * 32 + 63) / 64, 64>>>(u, p_sc, p_sf, p_u, p_uh, p_ul);

    // ---- segment counts ----
    cudaMemsetAsync(p_cd, 0, NN * sizeof(float));
    cudaMemsetAsync(p_cb, 0, NB * sizeof(float));
    count_idx<<<(NE + 255) / 256, 256>>>(dst, p_cd, NE);
    count_idx<<<(NN + 255) / 256, 256>>>(batch, p_cb, NN);
    make_inv<<<(NN + 255) / 256, 256>>>(p_cd, p_id, NN);
    make_inv<<<1, 64>>>(p_cb, p_ib, NB);

    // ---- pack edge weights into mma B-fragment order (hi/lo) ----
    bfrag_pack<<<(12 * 256 + 255) / 256, 256>>>(We[0], 192, p_bf + 0 * 16384);
    bfrag_pack<<<(16 * 256 + 255) / 256, 256>>>(We[1], 256, p_bf + 1 * 16384);
    bfrag_pack<<<(16 * 256 + 255) / 256, 256>>>(We[2], 256, p_bf + 2 * 16384);

    const int EGRID = (NE + 127) / 128;
    const int NGRID = 938;

    // ---- layer 0 ----
    cudaMemsetAsync(p_agg, 0, (size_t)NN * 64 * sizeof(float));
    edge_gemm<192, 32, false><<<EGRID, 256, SM192>>>(
        p_xh, p_xl, p_ehA, p_elA, p_uh, p_ul, src, dst, batch,
        p_bf + 0 * 16384, be[0], nullptr, p_ehB, p_elB, p_agg);
    cudaMemsetAsync(p_pool, 0, NB * 64 * sizeof(float));
    node_mlp<160, 32><<<NGRID, 256, 160 * 64 * 4>>>(p_x, p_agg, p_id, p_u, batch, Wn[0], bn[0], p_x, p_pool);
    glob_mlp<32><<<NB, 64>>>(p_pool, p_ib, p_u, Wg[0], bg[0], p_u);
    split_x<<<(NN * 64 + 255) / 256, 256>>>(p_x, p_xh, p_xl);
    split_u<<<(NB * 64 + 63) / 64, 64>>>(p_u, p_uh, p_ul);

    // ---- layer 1 ----
    cudaMemsetAsync(p_agg, 0, (size_t)NN * 64 * sizeof(float));
    edge_gemm<256, 64, false><<<EGRID, 256, SM256>>>(
        p_xh, p_xl, p_ehB, p_elB, p_uh, p_ul, src, dst, batch,
        p_bf + 1 * 16384, be[1], nullptr, p_ehA, p_elA, p_agg);
    cudaMemsetAsync(p_pool, 0, NB * 64 * sizeof(float));
    node_mlp<192, 64><<<NGRID, 256, 192 * 64 * 4>>>(p_x, p_agg, p_id, p_u, batch, Wn[1], bn[1], p_x, p_pool);
    glob_mlp<64><<<NB, 64>>>(p_pool, p_ib, p_u, Wg[1], bg[1], p_u);
    split_x<<<(NN * 64 + 255) / 256, 256>>>(p_x, p_xh, p_xl);
    split_u<<<(NB * 64 + 63) / 64, 64>>>(p_u, p_uh, p_ul);

    // ---- layer 2 (final: write out_e / out_x / out_u) ----
    cudaMemsetAsync(p_agg, 0, (size_t)NN * 64 * sizeof(float));
    edge_gemm<256, 64, true><<<EGRID, 256, SM256>>>(
        p_xh, p_xl, p_ehA, p_elA, p_uh, p_ul, src, dst, batch,
        p_bf + 2 * 16384, be[2], out_e, p_ehB, p_elB, p_agg);
    cudaMemsetAsync(p_pool, 0, NB * 64 * sizeof(float));
    node_mlp<192, 64><<<NGRID, 256, 192 * 64 * 4>>>(p_x, p_agg, p_id, p_u, batch, Wn[2], bn[2], out_x, p_pool);
    glob_mlp<64><<<NB, 64>>>(p_pool, p_ib, p_u, Wg[2], bg[2], out_u);
}